// round 2
// baseline (speedup 1.0000x reference)
#include <cuda_runtime.h>
#include <math.h>

// Problem dims
#define T_STEPS 128
#define BB      256     // batch
#define DIN     1024
#define HH      1024    // hidden = qdim
#define NQ      8
#define DD      2048    // DIN + HH
#define NC      4112    // zf(1024) | zi(1024) | gpre(1024) | opre(1024) | basef(8) | basei(8)

// -------- persistent device scratch (no allocations allowed) --------
__device__ float g_Wall[(size_t)NC * DD];   // folded weight stack, rows K-contiguous
__device__ float g_ball[NC];                // folded bias stack
__device__ float g_C[(size_t)BB * NC];      // per-step GEMM output
__device__ float g_HX[BB * HH];             // hidden state
__device__ float g_CX[BB * HH];             // cell state

// ---------------- GEMM config ----------------
#define BM 64
#define BN 128
#define BK 16

// Generic GEMM (prep only): C[m][n] = sum_k A[m*sA+k] * B[n*sBn + k*sBk]
__global__ __launch_bounds__(256) void gemm_generic(
    const float* __restrict__ A, int sA,
    const float* __restrict__ Bm, int sBn, int sBk,
    float* __restrict__ C, int ldc,
    int M, int N, int K)
{
    __shared__ float As[BK][BM + 1];
    __shared__ float Bs[BK][BN + 1];
    int tid = threadIdx.x;
    int tx = tid & 15, ty = tid >> 4;
    int m0 = blockIdx.y * BM, n0 = blockIdx.x * BN;
    float acc[4][8];
#pragma unroll
    for (int i = 0; i < 4; i++)
#pragma unroll
        for (int j = 0; j < 8; j++) acc[i][j] = 0.f;

    for (int k0 = 0; k0 < K; k0 += BK) {
#pragma unroll
        for (int r = 0; r < 4; r++) {
            int ml = ty + 16 * r;
            int m = m0 + ml;
            float v = 0.f;
            if (m < M) v = A[(size_t)m * sA + k0 + tx];
            As[tx][ml] = v;
        }
#pragma unroll
        for (int r = 0; r < 8; r++) {
            int nl = ty + 16 * r;
            int n = n0 + nl;
            float v = 0.f;
            if (n < N) v = Bm[(size_t)n * sBn + (size_t)(k0 + tx) * sBk];
            Bs[tx][nl] = v;
        }
        __syncthreads();
#pragma unroll
        for (int kk = 0; kk < BK; kk++) {
            float a[4], b[8];
#pragma unroll
            for (int i = 0; i < 4; i++) a[i] = As[kk][ty + 16 * i];
#pragma unroll
            for (int j = 0; j < 8; j++) b[j] = Bs[kk][tx + 16 * j];
#pragma unroll
            for (int i = 0; i < 4; i++)
#pragma unroll
                for (int j = 0; j < 8; j++) acc[i][j] += a[i] * b[j];
        }
        __syncthreads();
    }
#pragma unroll
    for (int i = 0; i < 4; i++) {
        int m = m0 + ty + 16 * i;
        if (m >= M) continue;
#pragma unroll
        for (int j = 0; j < 8; j++) {
            int n = n0 + tx + 16 * j;
            if (n < N) C[(size_t)m * ldc + n] = acc[i][j];
        }
    }
}

// Per-step main GEMM: C[256, 4112] = [x_t | hx] @ g_Wall^T + g_ball
__global__ __launch_bounds__(256) void gemm_main(const float* __restrict__ X)
{
    __shared__ float As[BK][BM + 1];
    __shared__ float Bs[BK][BN + 1];
    int tid = threadIdx.x;
    int tx = tid & 15, ty = tid >> 4;
    int m0 = blockIdx.y * BM, n0 = blockIdx.x * BN;
    float acc[4][8];
#pragma unroll
    for (int i = 0; i < 4; i++)
#pragma unroll
        for (int j = 0; j < 8; j++) acc[i][j] = 0.f;

    for (int k0 = 0; k0 < DD; k0 += BK) {
        const float* Asrc = (k0 < DIN) ? X : g_HX;
        int koff = (k0 < DIN) ? k0 : (k0 - DIN);
#pragma unroll
        for (int r = 0; r < 4; r++) {
            int ml = ty + 16 * r;
            As[tx][ml] = Asrc[(size_t)(m0 + ml) * 1024 + koff + tx];
        }
#pragma unroll
        for (int r = 0; r < 8; r++) {
            int nl = ty + 16 * r;
            int n = n0 + nl;
            Bs[tx][nl] = (n < NC) ? g_Wall[(size_t)n * DD + k0 + tx] : 0.f;
        }
        __syncthreads();
#pragma unroll
        for (int kk = 0; kk < BK; kk++) {
            float a[4], b[8];
#pragma unroll
            for (int i = 0; i < 4; i++) a[i] = As[kk][ty + 16 * i];
#pragma unroll
            for (int j = 0; j < 8; j++) b[j] = Bs[kk][tx + 16 * j];
#pragma unroll
            for (int i = 0; i < 4; i++)
#pragma unroll
                for (int j = 0; j < 8; j++) acc[i][j] += a[i] * b[j];
        }
        __syncthreads();
    }
#pragma unroll
    for (int i = 0; i < 4; i++) {
        int m = m0 + ty + 16 * i;
#pragma unroll
        for (int j = 0; j < 8; j++) {
            int n = n0 + tx + 16 * j;
            if (n < NC) g_C[(size_t)m * NC + n] = acc[i][j] + g_ball[n];
        }
    }
}

// --------- prep kernels ---------
__global__ void zero_state_kernel()
{
    int idx = blockIdx.x * blockDim.x + threadIdx.x;
    if (idx < BB * HH) { g_HX[idx] = 0.f; g_CX[idx] = 0.f; }
}

// Wall rows 2048..4095 <- Wu, Wo (verbatim)
__global__ void copy_wuwo_kernel(const float* __restrict__ Wu, const float* __restrict__ Wo)
{
    size_t idx = (size_t)blockIdx.x * blockDim.x + threadIdx.x;
    size_t total = (size_t)2 * 1024 * DD;
    if (idx < total) {
        float v = (idx < (size_t)1024 * DD) ? Wu[idx] : Wo[idx - (size_t)1024 * DD];
        g_Wall[(size_t)2048 * DD + idx] = v;
    }
}

// ball[0..2047] = enc_{f,i} @ bq ; ball[2048..4095] = bu,bo
__global__ void bias_enc_kernel(const float* __restrict__ encf, const float* __restrict__ enci,
                                const float* __restrict__ bq,
                                const float* __restrict__ bu, const float* __restrict__ bo)
{
    int n = blockIdx.x * blockDim.x + threadIdx.x;
    if (n < 2048) {
        const float* enc = (n < 1024) ? encf : enci;
        int row = n & 1023;
        float s = 0.f;
        for (int j = 0; j < 1024; j++) s += enc[row * 1024 + j] * bq[j];
        g_ball[n] = s;
    } else if (n < 3072) {
        g_ball[n] = bu[n - 2048];
    } else if (n < 4096) {
        g_ball[n] = bo[n - 3072];
    }
}

// Wall rows 4096..4111 = w_{f,i} @ Wall[rows of WqF/WqI]  (i.e. w@enc@Wq)
__global__ void wb_rows_kernel(const float* __restrict__ wfw, const float* __restrict__ wiw)
{
    int idx = blockIdx.x * blockDim.x + threadIdx.x;   // 16*2048
    if (idx >= 16 * DD) return;
    int i16 = idx / DD;       // 0..15
    int d = idx % DD;
    int g = i16 >> 3, i = i16 & 7;
    const float* ww = g ? wiw : wfw;
    float s = 0.f;
    for (int j = 0; j < 1024; j++)
        s += ww[i * 1024 + j] * g_Wall[((size_t)(g * 1024 + j)) * DD + d];
    g_Wall[(size_t)(4096 + i16) * DD + d] = s;
}

// ball[4096..4111] = w_{f,i} @ (enc_{f,i} @ bq)
__global__ void bias_wb_kernel(const float* __restrict__ wfw, const float* __restrict__ wiw)
{
    int t = threadIdx.x;
    if (t < 16) {
        int g = t >> 3, i = t & 7;
        const float* ww = g ? wiw : wfw;
        const float* bb = g_ball + g * 1024;
        float s = 0.f;
        for (int j = 0; j < 1024; j++) s += ww[i * 1024 + j] * bb[j];
        g_ball[4096 + t] = s;
    }
}

// --------- per-step small kernels ---------
// Sequential wire updates via rank-1 incremental corrections (8x8 triangle only)
__global__ void wire_kernel(const float* __restrict__ wfw, const float* __restrict__ wfb,
                            const float* __restrict__ wiw, const float* __restrict__ wib)
{
    int tid = threadIdx.x;      // 512 = 2 gates x 256 rows
    int g = tid >> 8;
    int b = tid & 255;
    const float* ww = g ? wiw : wfw;
    const float* wb = g ? wib : wfb;
    float* zrow = g_C + (size_t)b * NC + g * 1024;
    const float* base = g_C + (size_t)b * NC + 4096 + g * 8;

    float z8[NQ], delta[NQ];
#pragma unroll
    for (int k = 0; k < NQ; k++) z8[k] = zrow[k];
#pragma unroll
    for (int i = 0; i < NQ; i++) {
        float dot = base[i] + wb[i];
#pragma unroll
        for (int k = 0; k < NQ; k++)
            if (k < i) dot += delta[k] * ww[i * 1024 + k];
        float v = tanhf(dot);
        delta[i] = v - z8[i];
        z8[i] = v;
    }
#pragma unroll
    for (int k = 0; k < NQ; k++) zrow[k] = z8[k];
}

__device__ __forceinline__ float sigf(float x) { return 1.f / (1.f + expf(-x)); }

// Fused LSTM update: gates -> cx, hx, outs[t]
__global__ void elem_kernel(float* __restrict__ out_t)
{
    int idx = blockIdx.x * blockDim.x + threadIdx.x;   // B*H
    if (idx >= BB * HH) return;
    int b = idx >> 10, h = idx & 1023;
    const float* row = g_C + (size_t)b * NC;
    float f = sigf(row[h]);
    float ig = sigf(row[1024 + h]);
    float g = tanhf(row[2048 + h]);
    float o = sigf(row[3072 + h]);
    float c = f * g_CX[idx] + ig * g;
    g_CX[idx] = c;
    float hv = o * tanhf(c);
    g_HX[idx] = hv;
    out_t[idx] = hv;
}

__global__ void tail_kernel(float* __restrict__ out)
{
    int idx = blockIdx.x * blockDim.x + threadIdx.x;
    if (idx < BB * HH) {
        out[(size_t)T_STEPS * BB * HH + idx] = g_HX[idx];
        out[(size_t)T_STEPS * BB * HH + BB * HH + idx] = g_CX[idx];
    }
}

extern "C" void kernel_launch(void* const* d_in, const int* in_sizes, int n_in,
                              void* d_out, int out_size)
{
    const float* X    = (const float*)d_in[0];
    const float* Wq   = (const float*)d_in[1];
    const float* bq   = (const float*)d_in[2];
    const float* encf = (const float*)d_in[3];
    const float* wfw  = (const float*)d_in[4];
    const float* wfb  = (const float*)d_in[5];
    const float* enci = (const float*)d_in[6];
    const float* wiw  = (const float*)d_in[7];
    const float* wib  = (const float*)d_in[8];
    const float* Wu   = (const float*)d_in[9];
    const float* bu   = (const float*)d_in[10];
    const float* Wo   = (const float*)d_in[11];
    const float* bo   = (const float*)d_in[12];
    float* out = (float*)d_out;

    float* Wall = nullptr;
    cudaGetSymbolAddress((void**)&Wall, g_Wall);

    // ---- prep (runs inside the graph; deterministic) ----
    zero_state_kernel<<<(BB * HH + 255) / 256, 256>>>();
    {
        size_t total = (size_t)2 * 1024 * DD;
        copy_wuwo_kernel<<<(unsigned)((total + 255) / 256), 256>>>(Wu, Wo);
    }
    bias_enc_kernel<<<16, 256>>>(encf, enci, bq, bu, bo);
    // WqF = enc_f @ Wq -> Wall rows [0,1024)
    gemm_generic<<<dim3((DD + BN - 1) / BN, (1024 + BM - 1) / BM), 256>>>(
        encf, 1024, Wq, 1, DD, Wall, DD, 1024, DD, 1024);
    // WqI = enc_i @ Wq -> Wall rows [1024,2048)
    gemm_generic<<<dim3((DD + BN - 1) / BN, (1024 + BM - 1) / BM), 256>>>(
        enci, 1024, Wq, 1, DD, Wall + (size_t)1024 * DD, DD, 1024, DD, 1024);
    wb_rows_kernel<<<(16 * DD + 255) / 256, 256>>>(wfw, wiw);
    bias_wb_kernel<<<1, 32>>>(wfw, wiw);

    // ---- recurrence ----
    dim3 grid_main((NC + BN - 1) / BN, (BB + BM - 1) / BM);  // 33 x 4
    for (int t = 0; t < T_STEPS; t++) {
        gemm_main<<<grid_main, 256>>>(X + (size_t)t * BB * DIN);
        wire_kernel<<<1, 512>>>(wfw, wfb, wiw, wib);
        elem_kernel<<<(BB * HH + 255) / 256, 256>>>(out + (size_t)t * BB * HH);
    }
    tail_kernel<<<(BB * HH + 255) / 256, 256>>>(out);
}

// round 3
// speedup vs baseline: 1.0001x; 1.0001x over previous
#include <cuda_runtime.h>
#include <math.h>

// Problem dims
#define T_STEPS 128
#define BB      256     // batch
#define DIN     1024
#define HH      1024    // hidden = qdim
#define NQ      8
#define DD      2048    // DIN + HH
#define NC      4112    // zf(1024) | zi(1024) | gpre(1024) | opre(1024) | basef(8) | basei(8)

// -------- persistent device scratch (no allocations allowed) --------
__device__ float g_Wall[(size_t)NC * DD];   // folded weight stack, rows K-contiguous
__device__ float g_ball[NC];                // folded bias stack
__device__ float g_C[(size_t)BB * NC];      // per-step GEMM output
__device__ float g_HX[BB * HH];             // hidden state
__device__ float g_CX[BB * HH];             // cell state

// ---------------- GEMM config ----------------
#define BM 64
#define BN 128
#define BK 16

// Generic GEMM (prep only): C[m][n] = sum_k A[m*sA+k] * B[n*sBn + k*sBk]
__global__ __launch_bounds__(256) void gemm_generic(
    const float* __restrict__ A, int sA,
    const float* __restrict__ Bm, int sBn, int sBk,
    float* __restrict__ C, int ldc,
    int M, int N, int K)
{
    __shared__ float As[BK][BM + 1];
    __shared__ float Bs[BK][BN + 1];
    int tid = threadIdx.x;
    int tx = tid & 15, ty = tid >> 4;
    int m0 = blockIdx.y * BM, n0 = blockIdx.x * BN;
    float acc[4][8];
#pragma unroll
    for (int i = 0; i < 4; i++)
#pragma unroll
        for (int j = 0; j < 8; j++) acc[i][j] = 0.f;

    for (int k0 = 0; k0 < K; k0 += BK) {
#pragma unroll
        for (int r = 0; r < 4; r++) {
            int ml = ty + 16 * r;
            int m = m0 + ml;
            float v = 0.f;
            if (m < M) v = A[(size_t)m * sA + k0 + tx];
            As[tx][ml] = v;
        }
#pragma unroll
        for (int r = 0; r < 8; r++) {
            int nl = ty + 16 * r;
            int n = n0 + nl;
            float v = 0.f;
            if (n < N) v = Bm[(size_t)n * sBn + (size_t)(k0 + tx) * sBk];
            Bs[tx][nl] = v;
        }
        __syncthreads();
#pragma unroll
        for (int kk = 0; kk < BK; kk++) {
            float a[4], b[8];
#pragma unroll
            for (int i = 0; i < 4; i++) a[i] = As[kk][ty + 16 * i];
#pragma unroll
            for (int j = 0; j < 8; j++) b[j] = Bs[kk][tx + 16 * j];
#pragma unroll
            for (int i = 0; i < 4; i++)
#pragma unroll
                for (int j = 0; j < 8; j++) acc[i][j] += a[i] * b[j];
        }
        __syncthreads();
    }
#pragma unroll
    for (int i = 0; i < 4; i++) {
        int m = m0 + ty + 16 * i;
        if (m >= M) continue;
#pragma unroll
        for (int j = 0; j < 8; j++) {
            int n = n0 + tx + 16 * j;
            if (n < N) C[(size_t)m * ldc + n] = acc[i][j];
        }
    }
}

// Per-step main GEMM: C[256, 4112] = [x_t | hx] @ g_Wall^T + g_ball
__global__ __launch_bounds__(256) void gemm_main(const float* __restrict__ X)
{
    __shared__ float As[BK][BM + 1];
    __shared__ float Bs[BK][BN + 1];
    int tid = threadIdx.x;
    int tx = tid & 15, ty = tid >> 4;
    int m0 = blockIdx.y * BM, n0 = blockIdx.x * BN;
    float acc[4][8];
#pragma unroll
    for (int i = 0; i < 4; i++)
#pragma unroll
        for (int j = 0; j < 8; j++) acc[i][j] = 0.f;

    for (int k0 = 0; k0 < DD; k0 += BK) {
        const float* Asrc = (k0 < DIN) ? X : g_HX;
        int koff = (k0 < DIN) ? k0 : (k0 - DIN);
#pragma unroll
        for (int r = 0; r < 4; r++) {
            int ml = ty + 16 * r;
            As[tx][ml] = Asrc[(size_t)(m0 + ml) * 1024 + koff + tx];
        }
#pragma unroll
        for (int r = 0; r < 8; r++) {
            int nl = ty + 16 * r;
            int n = n0 + nl;
            Bs[tx][nl] = (n < NC) ? g_Wall[(size_t)n * DD + k0 + tx] : 0.f;
        }
        __syncthreads();
#pragma unroll
        for (int kk = 0; kk < BK; kk++) {
            float a[4], b[8];
#pragma unroll
            for (int i = 0; i < 4; i++) a[i] = As[kk][ty + 16 * i];
#pragma unroll
            for (int j = 0; j < 8; j++) b[j] = Bs[kk][tx + 16 * j];
#pragma unroll
            for (int i = 0; i < 4; i++)
#pragma unroll
                for (int j = 0; j < 8; j++) acc[i][j] += a[i] * b[j];
        }
        __syncthreads();
    }
#pragma unroll
    for (int i = 0; i < 4; i++) {
        int m = m0 + ty + 16 * i;
#pragma unroll
        for (int j = 0; j < 8; j++) {
            int n = n0 + tx + 16 * j;
            if (n < NC) g_C[(size_t)m * NC + n] = acc[i][j] + g_ball[n];
        }
    }
}

// --------- prep kernels ---------
__global__ void zero_state_kernel()
{
    int idx = blockIdx.x * blockDim.x + threadIdx.x;
    if (idx < BB * HH) { g_HX[idx] = 0.f; g_CX[idx] = 0.f; }
}

// Wall rows 2048..4095 <- Wu, Wo (verbatim)
__global__ void copy_wuwo_kernel(const float* __restrict__ Wu, const float* __restrict__ Wo)
{
    size_t idx = (size_t)blockIdx.x * blockDim.x + threadIdx.x;
    size_t total = (size_t)2 * 1024 * DD;
    if (idx < total) {
        float v = (idx < (size_t)1024 * DD) ? Wu[idx] : Wo[idx - (size_t)1024 * DD];
        g_Wall[(size_t)2048 * DD + idx] = v;
    }
}

// ball[0..2047] = enc_{f,i} @ bq ; ball[2048..4095] = bu,bo
__global__ void bias_enc_kernel(const float* __restrict__ encf, const float* __restrict__ enci,
                                const float* __restrict__ bq,
                                const float* __restrict__ bu, const float* __restrict__ bo)
{
    int n = blockIdx.x * blockDim.x + threadIdx.x;
    if (n < 2048) {
        const float* enc = (n < 1024) ? encf : enci;
        int row = n & 1023;
        float s = 0.f;
        for (int j = 0; j < 1024; j++) s += enc[row * 1024 + j] * bq[j];
        g_ball[n] = s;
    } else if (n < 3072) {
        g_ball[n] = bu[n - 2048];
    } else if (n < 4096) {
        g_ball[n] = bo[n - 3072];
    }
}

// Wall rows 4096..4111 = w_{f,i} @ Wall[rows of WqF/WqI]  (i.e. w@enc@Wq)
__global__ void wb_rows_kernel(const float* __restrict__ wfw, const float* __restrict__ wiw)
{
    int idx = blockIdx.x * blockDim.x + threadIdx.x;   // 16*2048
    if (idx >= 16 * DD) return;
    int i16 = idx / DD;       // 0..15
    int d = idx % DD;
    int g = i16 >> 3, i = i16 & 7;
    const float* ww = g ? wiw : wfw;
    float s = 0.f;
    for (int j = 0; j < 1024; j++)
        s += ww[i * 1024 + j] * g_Wall[((size_t)(g * 1024 + j)) * DD + d];
    g_Wall[(size_t)(4096 + i16) * DD + d] = s;
}

// ball[4096..4111] = w_{f,i} @ (enc_{f,i} @ bq)
__global__ void bias_wb_kernel(const float* __restrict__ wfw, const float* __restrict__ wiw)
{
    int t = threadIdx.x;
    if (t < 16) {
        int g = t >> 3, i = t & 7;
        const float* ww = g ? wiw : wfw;
        const float* bb = g_ball + g * 1024;
        float s = 0.f;
        for (int j = 0; j < 1024; j++) s += ww[i * 1024 + j] * bb[j];
        g_ball[4096 + t] = s;
    }
}

// --------- per-step small kernels ---------
// Sequential wire updates via rank-1 incremental corrections (8x8 triangle only)
__global__ void wire_kernel(const float* __restrict__ wfw, const float* __restrict__ wfb,
                            const float* __restrict__ wiw, const float* __restrict__ wib)
{
    int tid = threadIdx.x;      // 512 = 2 gates x 256 rows
    int g = tid >> 8;
    int b = tid & 255;
    const float* ww = g ? wiw : wfw;
    const float* wb = g ? wib : wfb;
    float* zrow = g_C + (size_t)b * NC + g * 1024;
    const float* base = g_C + (size_t)b * NC + 4096 + g * 8;

    float z8[NQ], delta[NQ];
#pragma unroll
    for (int k = 0; k < NQ; k++) z8[k] = zrow[k];
#pragma unroll
    for (int i = 0; i < NQ; i++) {
        float dot = base[i] + wb[i];
#pragma unroll
        for (int k = 0; k < NQ; k++)
            if (k < i) dot += delta[k] * ww[i * 1024 + k];
        float v = tanhf(dot);
        delta[i] = v - z8[i];
        z8[i] = v;
    }
#pragma unroll
    for (int k = 0; k < NQ; k++) zrow[k] = z8[k];
}

__device__ __forceinline__ float sigf(float x) { return 1.f / (1.f + expf(-x)); }

// Fused LSTM update: gates -> cx, hx, outs[t]
__global__ void elem_kernel(float* __restrict__ out_t)
{
    int idx = blockIdx.x * blockDim.x + threadIdx.x;   // B*H
    if (idx >= BB * HH) return;
    int b = idx >> 10, h = idx & 1023;
    const float* row = g_C + (size_t)b * NC;
    float f = sigf(row[h]);
    float ig = sigf(row[1024 + h]);
    float g = tanhf(row[2048 + h]);
    float o = sigf(row[3072 + h]);
    float c = f * g_CX[idx] + ig * g;
    g_CX[idx] = c;
    float hv = o * tanhf(c);
    g_HX[idx] = hv;
    out_t[idx] = hv;
}

__global__ void tail_kernel(float* __restrict__ out)
{
    int idx = blockIdx.x * blockDim.x + threadIdx.x;
    if (idx < BB * HH) {
        out[(size_t)T_STEPS * BB * HH + idx] = g_HX[idx];
        out[(size_t)T_STEPS * BB * HH + BB * HH + idx] = g_CX[idx];
    }
}

extern "C" void kernel_launch(void* const* d_in, const int* in_sizes, int n_in,
                              void* d_out, int out_size)
{
    const float* X    = (const float*)d_in[0];
    const float* Wq   = (const float*)d_in[1];
    const float* bq   = (const float*)d_in[2];
    const float* encf = (const float*)d_in[3];
    const float* wfw  = (const float*)d_in[4];
    const float* wfb  = (const float*)d_in[5];
    const float* enci = (const float*)d_in[6];
    const float* wiw  = (const float*)d_in[7];
    const float* wib  = (const float*)d_in[8];
    const float* Wu   = (const float*)d_in[9];
    const float* bu   = (const float*)d_in[10];
    const float* Wo   = (const float*)d_in[11];
    const float* bo   = (const float*)d_in[12];
    float* out = (float*)d_out;

    float* Wall = nullptr;
    cudaGetSymbolAddress((void**)&Wall, g_Wall);

    // ---- prep (runs inside the graph; deterministic) ----
    zero_state_kernel<<<(BB * HH + 255) / 256, 256>>>();
    {
        size_t total = (size_t)2 * 1024 * DD;
        copy_wuwo_kernel<<<(unsigned)((total + 255) / 256), 256>>>(Wu, Wo);
    }
    bias_enc_kernel<<<16, 256>>>(encf, enci, bq, bu, bo);
    // WqF = enc_f @ Wq -> Wall rows [0,1024)
    gemm_generic<<<dim3((DD + BN - 1) / BN, (1024 + BM - 1) / BM), 256>>>(
        encf, 1024, Wq, 1, DD, Wall, DD, 1024, DD, 1024);
    // WqI = enc_i @ Wq -> Wall rows [1024,2048)
    gemm_generic<<<dim3((DD + BN - 1) / BN, (1024 + BM - 1) / BM), 256>>>(
        enci, 1024, Wq, 1, DD, Wall + (size_t)1024 * DD, DD, 1024, DD, 1024);
    wb_rows_kernel<<<(16 * DD + 255) / 256, 256>>>(wfw, wiw);
    bias_wb_kernel<<<1, 32>>>(wfw, wiw);

    // ---- recurrence ----
    dim3 grid_main((NC + BN - 1) / BN, (BB + BM - 1) / BM);  // 33 x 4
    for (int t = 0; t < T_STEPS; t++) {
        gemm_main<<<grid_main, 256>>>(X + (size_t)t * BB * DIN);
        wire_kernel<<<1, 512>>>(wfw, wfb, wiw, wib);
        elem_kernel<<<(BB * HH + 255) / 256, 256>>>(out + (size_t)t * BB * HH);
    }
    tail_kernel<<<(BB * HH + 255) / 256, 256>>>(out);
}

// round 6
// speedup vs baseline: 2.5154x; 2.5152x over previous
#include <cuda_runtime.h>
#include <cuda.h>
#include <cuda_bf16.h>
#include <math.h>
#include <stdint.h>

// Problem dims
#define T_STEPS 128
#define BB      256
#define DIN     1024
#define HH      1024
#define NQ      8
#define DD      2048          // DIN + HH
#define NC      4112          // useful columns: zf|zi|g|o|basef(8)|basei(8)
#define NPAD    4224          // padded to 33 tiles of 128
#define K3      6144          // 3 * DD (bf16-3x folded K)

// ---------------- persistent device scratch ----------------
__device__ float g_Wall[(size_t)NC * DD];            // folded fp32 weights
__device__ float g_ball[NPAD];                       // bias (padded)
__device__ __align__(256) __nv_bfloat16 g_Bp[(size_t)NPAD * K3];  // [Bhi|Bhi|Blo]
__device__ __align__(256) __nv_bfloat16 g_Ap[(size_t)BB * K3];    // [Ahi|Alo|Ahi]
__device__ float g_CT[(size_t)NPAD * BB];            // C transposed: [n][b]
__device__ float g_CXT[HH * BB];                     // cell state  [h][b]
__device__ float g_HXT[HH * BB];                     // hidden     [h][b]

// ============================================================
// mma.sync step GEMM: C^T[4224,256] = (A'[256,6144] @ B'[4224,6144]^T)^T + bias
// Block tile 64(M) x 128(N), BK=32, 3-stage cp.async pipeline, 8 warps.
// ============================================================
#define BKG   32
#define STG   3
#define NT    (K3 / BKG)          // 192
#define APITCH 40                 // bf16 elems per smem row (32 + 8 pad) = 80B
#define A_STAGE_B (64 * APITCH * 2)    // 5120 B
#define B_STAGE_B (128 * APITCH * 2)   // 10240 B

__device__ __forceinline__ uint32_t smem_u32(const void* p) {
    uint32_t a;
    asm("{ .reg .u64 t; cvta.to.shared.u64 t, %1; cvt.u32.u64 %0, t; }" : "=r"(a) : "l"(p));
    return a;
}
__device__ __forceinline__ void cp_async16(uint32_t dst, const void* src) {
    asm volatile("cp.async.cg.shared.global [%0], [%1], 16;" :: "r"(dst), "l"(src));
}
__device__ __forceinline__ void ldmatrix_x4(uint32_t& r0, uint32_t& r1,
                                            uint32_t& r2, uint32_t& r3, uint32_t a) {
    asm volatile("ldmatrix.sync.aligned.m8n8.x4.shared.b16 {%0,%1,%2,%3}, [%4];"
                 : "=r"(r0), "=r"(r1), "=r"(r2), "=r"(r3) : "r"(a));
}
__device__ __forceinline__ void mma_bf16(float* c, const uint32_t* a,
                                         uint32_t b0, uint32_t b1) {
    asm volatile("mma.sync.aligned.m16n8k16.row.col.f32.bf16.bf16.f32 "
                 "{%0,%1,%2,%3}, {%4,%5,%6,%7}, {%8,%9}, {%0,%1,%2,%3};"
                 : "+f"(c[0]), "+f"(c[1]), "+f"(c[2]), "+f"(c[3])
                 : "r"(a[0]), "r"(a[1]), "r"(a[2]), "r"(a[3]), "r"(b0), "r"(b1));
}

__global__ __launch_bounds__(256, 1) void gemm_mma()
{
    __shared__ __align__(16) __nv_bfloat16 As[STG][64][APITCH];
    __shared__ __align__(16) __nv_bfloat16 Bs[STG][128][APITCH];

    const int tid = threadIdx.x, lane = tid & 31, wid = tid >> 5;
    const int wm = wid & 1, wn = wid >> 1;        // warp 32x32 tile: (wm*32, wn*32)
    const int m0 = blockIdx.y * 64, n0 = blockIdx.x * 128;

    const uint32_t asb = smem_u32(&As[0][0][0]);
    const uint32_t bsb = smem_u32(&Bs[0][0][0]);

    // per-thread load geometry: 16B chunks
    const int lrow = tid >> 2, lcol = tid & 3;   // A: row 0..63, col chunk 0..3
    const __nv_bfloat16* gA  = g_Ap + (size_t)(m0 + lrow) * K3 + lcol * 8;
    const __nv_bfloat16* gB0 = g_Bp + (size_t)(n0 + lrow) * K3 + lcol * 8;
    const __nv_bfloat16* gB1 = g_Bp + (size_t)(n0 + 64 + lrow) * K3 + lcol * 8;
    const uint32_t dA  = asb + (lrow * APITCH + lcol * 8) * 2;
    const uint32_t dB0 = bsb + (lrow * APITCH + lcol * 8) * 2;
    const uint32_t dB1 = bsb + ((64 + lrow) * APITCH + lcol * 8) * 2;

    float acc[2][4][4];
#pragma unroll
    for (int i = 0; i < 2; i++)
#pragma unroll
        for (int j = 0; j < 4; j++)
#pragma unroll
            for (int r = 0; r < 4; r++) acc[i][j][r] = 0.f;

    // ldmatrix source addresses (per k16-half add offset later)
    const uint32_t aAddr0 = asb + ((wm * 32 + (lane & 15)) * APITCH + (lane >> 4) * 8) * 2;
    const int brow = wn * 32 + (lane & 7) + ((lane >> 4) << 3);
    const uint32_t bAddr0 = bsb + (brow * APITCH + (((lane >> 3) & 1) << 3)) * 2;

    // prologue: stages 0..STG-2
#pragma unroll
    for (int s = 0; s < STG - 1; s++) {
        int k = s * BKG;
        cp_async16(dA + s * A_STAGE_B, gA + k);
        cp_async16(dB0 + s * B_STAGE_B, gB0 + k);
        cp_async16(dB1 + s * B_STAGE_B, gB1 + k);
        asm volatile("cp.async.commit_group;");
    }

    for (int kt = 0; kt < NT; kt++) {
        asm volatile("cp.async.wait_group %0;" :: "n"(STG - 2));
        __syncthreads();
        const int st = kt % STG;
        const uint32_t aB = aAddr0 + st * A_STAGE_B;
        const uint32_t bB = bAddr0 + st * B_STAGE_B;
#pragma unroll
        for (int kk = 0; kk < 2; kk++) {           // two k16 halves of BK=32
            uint32_t a[2][4], b[2][4];
#pragma unroll
            for (int mf = 0; mf < 2; mf++)
                ldmatrix_x4(a[mf][0], a[mf][1], a[mf][2], a[mf][3],
                            aB + (mf * 16 * APITCH + kk * 16) * 2);
#pragma unroll
            for (int nf = 0; nf < 2; nf++)
                ldmatrix_x4(b[nf][0], b[nf][1], b[nf][2], b[nf][3],
                            bB + (nf * 16 * APITCH + kk * 16) * 2);
#pragma unroll
            for (int mf = 0; mf < 2; mf++)
#pragma unroll
                for (int nf = 0; nf < 2; nf++) {
                    mma_bf16(acc[mf][nf * 2 + 0], a[mf], b[nf][0], b[nf][1]);
                    mma_bf16(acc[mf][nf * 2 + 1], a[mf], b[nf][2], b[nf][3]);
                }
        }
        __syncthreads();
        const int nk = kt + STG - 1;
        if (nk < NT) {
            const int s2 = nk % STG, k = nk * BKG;
            cp_async16(dA + s2 * A_STAGE_B, gA + k);
            cp_async16(dB0 + s2 * B_STAGE_B, gB0 + k);
            cp_async16(dB1 + s2 * B_STAGE_B, gB1 + k);
        }
        asm volatile("cp.async.commit_group;");
    }

    // epilogue: scatter into g_CT[n][m] with bias
#pragma unroll
    for (int mf = 0; mf < 2; mf++) {
        const int mb = m0 + wm * 32 + mf * 16 + (lane >> 2);
#pragma unroll
        for (int q = 0; q < 4; q++) {
            const int nb = n0 + wn * 32 + q * 8 + 2 * (lane & 3);
            const float bl0 = __ldg(&g_ball[nb]), bl1 = __ldg(&g_ball[nb + 1]);
            g_CT[(size_t)nb * BB + mb]           = acc[mf][q][0] + bl0;
            g_CT[(size_t)(nb + 1) * BB + mb]     = acc[mf][q][1] + bl1;
            g_CT[(size_t)nb * BB + mb + 8]       = acc[mf][q][2] + bl0;
            g_CT[(size_t)(nb + 1) * BB + mb + 8] = acc[mf][q][3] + bl1;
        }
    }
}

// ============================================================
// prep kernels
// ============================================================
#define BM 64
#define BN 128
#define BK 16
__global__ __launch_bounds__(256) void gemm_generic(
    const float* __restrict__ A, int sA,
    const float* __restrict__ Bm, int sBn, int sBk,
    float* __restrict__ C, int ldc, int M, int N, int K)
{
    __shared__ float Ash[BK][BM + 1];
    __shared__ float Bsh[BK][BN + 1];
    int tid = threadIdx.x, tx = tid & 15, ty = tid >> 4;
    int m0 = blockIdx.y * BM, n0 = blockIdx.x * BN;
    float acc[4][8];
#pragma unroll
    for (int i = 0; i < 4; i++)
#pragma unroll
        for (int j = 0; j < 8; j++) acc[i][j] = 0.f;
    for (int k0 = 0; k0 < K; k0 += BK) {
#pragma unroll
        for (int r = 0; r < 4; r++) {
            int ml = ty + 16 * r, mm = m0 + ml;
            Ash[tx][ml] = (mm < M) ? A[(size_t)mm * sA + k0 + tx] : 0.f;
        }
#pragma unroll
        for (int r = 0; r < 8; r++) {
            int nl = ty + 16 * r, nn = n0 + nl;
            Bsh[tx][nl] = (nn < N) ? Bm[(size_t)nn * sBn + (size_t)(k0 + tx) * sBk] : 0.f;
        }
        __syncthreads();
#pragma unroll
        for (int kk = 0; kk < BK; kk++) {
            float a[4], b[8];
#pragma unroll
            for (int i = 0; i < 4; i++) a[i] = Ash[kk][ty + 16 * i];
#pragma unroll
            for (int j = 0; j < 8; j++) b[j] = Bsh[kk][tx + 16 * j];
#pragma unroll
            for (int i = 0; i < 4; i++)
#pragma unroll
                for (int j = 0; j < 8; j++) acc[i][j] += a[i] * b[j];
        }
        __syncthreads();
    }
#pragma unroll
    for (int i = 0; i < 4; i++) {
        int mm = m0 + ty + 16 * i;
        if (mm >= M) continue;
#pragma unroll
        for (int j = 0; j < 8; j++) {
            int nn = n0 + tx + 16 * j;
            if (nn < N) C[(size_t)mm * ldc + nn] = acc[i][j];
        }
    }
}

__global__ void zero_state_kernel() {
    int idx = blockIdx.x * blockDim.x + threadIdx.x;
    if (idx < HH * BB) { g_HXT[idx] = 0.f; g_CXT[idx] = 0.f; }
}
__global__ void zero_ap_kernel() {
    int idx = blockIdx.x * blockDim.x + threadIdx.x;
    if (idx < BB * K3) g_Ap[idx] = __float2bfloat16(0.f);
}
__global__ void copy_wuwo_kernel(const float* __restrict__ Wu, const float* __restrict__ Wo) {
    size_t idx = (size_t)blockIdx.x * blockDim.x + threadIdx.x;
    size_t total = (size_t)2 * 1024 * DD;
    if (idx < total) {
        float v = (idx < (size_t)1024 * DD) ? Wu[idx] : Wo[idx - (size_t)1024 * DD];
        g_Wall[(size_t)2048 * DD + idx] = v;
    }
}
__global__ void bias_enc_kernel(const float* __restrict__ encf, const float* __restrict__ enci,
                                const float* __restrict__ bq,
                                const float* __restrict__ bu, const float* __restrict__ bo) {
    int n = blockIdx.x * blockDim.x + threadIdx.x;
    if (n < 2048) {
        const float* enc = (n < 1024) ? encf : enci;
        int row = n & 1023;
        float s = 0.f;
        for (int j = 0; j < 1024; j++) s += enc[row * 1024 + j] * bq[j];
        g_ball[n] = s;
    } else if (n < 3072) g_ball[n] = bu[n - 2048];
    else if (n < 4096) g_ball[n] = bo[n - 3072];
    else if (n >= 4112 && n < NPAD) g_ball[n] = 0.f;
}
__global__ void wb_rows_kernel(const float* __restrict__ wfw, const float* __restrict__ wiw) {
    int idx = blockIdx.x * blockDim.x + threadIdx.x;
    if (idx >= 16 * DD) return;
    int i16 = idx / DD, d = idx % DD;
    int g = i16 >> 3, i = i16 & 7;
    const float* ww = g ? wiw : wfw;
    float s = 0.f;
    for (int j = 0; j < 1024; j++)
        s += ww[i * 1024 + j] * g_Wall[((size_t)(g * 1024 + j)) * DD + d];
    g_Wall[(size_t)(4096 + i16) * DD + d] = s;
}
__global__ void bias_wb_kernel(const float* __restrict__ wfw, const float* __restrict__ wiw) {
    int t = threadIdx.x;
    if (t < 16) {
        int g = t >> 3, i = t & 7;
        const float* ww = g ? wiw : wfw;
        const float* bb = g_ball + g * 1024;
        float s = 0.f;
        for (int j = 0; j < 1024; j++) s += ww[i * 1024 + j] * bb[j];
        g_ball[4096 + t] = s;
    }
}
// B' = [Bhi | Bhi | Blo], rows >= NC zero-padded
__global__ void bsplit_kernel() {
    size_t idx = (size_t)blockIdx.x * blockDim.x + threadIdx.x;
    if (idx >= (size_t)NPAD * K3) return;
    int n = (int)(idx / K3), c = (int)(idx % K3);
    float v = 0.f;
    if (n < NC) {
        int k = (c < 2048) ? c : ((c < 4096) ? c - 2048 : c - 4096);
        v = g_Wall[(size_t)n * DD + k];
    }
    __nv_bfloat16 hi = __float2bfloat16(v);
    g_Bp[idx] = (c < 4096) ? hi : __float2bfloat16(v - __bfloat162float(hi));
}

// ============================================================
// per-step small kernels
// ============================================================
// A' x-part: cols [0,1024)=hi, [2048,3072)=lo, [4096,5120)=hi
__global__ void aprep_kernel(const float* __restrict__ X) {
    int idx = blockIdx.x * blockDim.x + threadIdx.x;
    if (idx >= BB * 1024) return;
    int b = idx >> 10, k = idx & 1023;
    float v = X[idx];
    __nv_bfloat16 hi = __float2bfloat16(v);
    __nv_bfloat16 lo = __float2bfloat16(v - __bfloat162float(hi));
    size_t base = (size_t)b * K3;
    g_Ap[base + k] = hi;
    g_Ap[base + 2048 + k] = lo;
    g_Ap[base + 4096 + k] = hi;
}

// wire updates on transposed C
__global__ void wire_kernel(const float* __restrict__ wfw, const float* __restrict__ wfb,
                            const float* __restrict__ wiw, const float* __restrict__ wib) {
    int tid = threadIdx.x;   // 512 = 2 gates x 256 batch
    int g = tid >> 8, b = tid & 255;
    const float* ww = g ? wiw : wfw;
    const float* wb = g ? wib : wfb;
    float* zc = g_CT + (size_t)(g * 1024) * BB + b;
    const float* base = g_CT + (size_t)(4096 + g * 8) * BB + b;

    float z8[NQ], delta[NQ];
#pragma unroll
    for (int k = 0; k < NQ; k++) z8[k] = zc[(size_t)k * BB];
#pragma unroll
    for (int i = 0; i < NQ; i++) {
        float dot = base[(size_t)i * BB] + wb[i];
#pragma unroll
        for (int k = 0; k < NQ; k++)
            if (k < i) dot += delta[k] * ww[i * 1024 + k];
        float v = tanhf(dot);
        delta[i] = v - z8[i];
        z8[i] = v;
    }
#pragma unroll
    for (int k = 0; k < NQ; k++) zc[(size_t)k * BB] = z8[k];
}

__device__ __forceinline__ float sigf(float x) { return 1.f / (1.f + expf(-x)); }

// LSTM update: reads C^T, updates state, writes outs[t] and A' hx-parts
__global__ void elem_kernel(float* __restrict__ out_t) {
    int idx = blockIdx.x * blockDim.x + threadIdx.x;
    if (idx >= BB * HH) return;
    int b = idx & 255, h = idx >> 8;
    size_t p = (size_t)h * BB + b;
    float f  = sigf(g_CT[p]);
    float ig = sigf(g_CT[(size_t)(1024 + h) * BB + b]);
    float gg = tanhf(g_CT[(size_t)(2048 + h) * BB + b]);
    float o  = sigf(g_CT[(size_t)(3072 + h) * BB + b]);
    float c = f * g_CXT[p] + ig * gg;
    g_CXT[p] = c;
    float hv = o * tanhf(c);
    g_HXT[p] = hv;
    out_t[(size_t)b * HH + h] = hv;
    __nv_bfloat16 hi = __float2bfloat16(hv);
    __nv_bfloat16 lo = __float2bfloat16(hv - __bfloat162float(hi));
    size_t base = (size_t)b * K3;
    g_Ap[base + 1024 + h] = hi;
    g_Ap[base + 3072 + h] = lo;
    g_Ap[base + 5120 + h] = hi;
}

__global__ void tail_kernel(float* __restrict__ out) {
    int idx = blockIdx.x * blockDim.x + threadIdx.x;
    if (idx < BB * HH) {
        int h = idx & 1023, b = idx >> 10;
        out[(size_t)T_STEPS * BB * HH + idx] = g_HXT[(size_t)h * BB + b];
        out[(size_t)T_STEPS * BB * HH + BB * HH + idx] = g_CXT[(size_t)h * BB + b];
    }
}

// ============================================================
// host
// ============================================================
extern "C" void kernel_launch(void* const* d_in, const int* in_sizes, int n_in,
                              void* d_out, int out_size)
{
    const float* X    = (const float*)d_in[0];
    const float* Wq   = (const float*)d_in[1];
    const float* bq   = (const float*)d_in[2];
    const float* encf = (const float*)d_in[3];
    const float* wfw  = (const float*)d_in[4];
    const float* wfb  = (const float*)d_in[5];
    const float* enci = (const float*)d_in[6];
    const float* wiw  = (const float*)d_in[7];
    const float* wib  = (const float*)d_in[8];
    const float* Wu   = (const float*)d_in[9];
    const float* bu   = (const float*)d_in[10];
    const float* Wo   = (const float*)d_in[11];
    const float* bo   = (const float*)d_in[12];
    float* out = (float*)d_out;

    float* Wall = nullptr; cudaGetSymbolAddress((void**)&Wall, g_Wall);

    // ---- prep ----
    zero_state_kernel<<<(HH * BB + 255) / 256, 256>>>();
    zero_ap_kernel<<<(BB * K3 + 255) / 256, 256>>>();
    {
        size_t total = (size_t)2 * 1024 * DD;
        copy_wuwo_kernel<<<(unsigned)((total + 255) / 256), 256>>>(Wu, Wo);
    }
    bias_enc_kernel<<<(NPAD + 255) / 256, 256>>>(encf, enci, bq, bu, bo);
    gemm_generic<<<dim3((DD + BN - 1) / BN, (1024 + BM - 1) / BM), 256>>>(
        encf, 1024, Wq, 1, DD, Wall, DD, 1024, DD, 1024);
    gemm_generic<<<dim3((DD + BN - 1) / BN, (1024 + BM - 1) / BM), 256>>>(
        enci, 1024, Wq, 1, DD, Wall + (size_t)1024 * DD, DD, 1024, DD, 1024);
    wb_rows_kernel<<<(16 * DD + 255) / 256, 256>>>(wfw, wiw);
    bias_wb_kernel<<<1, 32>>>(wfw, wiw);
    {
        size_t total = (size_t)NPAD * K3;
        bsplit_kernel<<<(unsigned)((total + 255) / 256), 256>>>();
    }

    // ---- recurrence ----
    dim3 grid_mma(NPAD / 128, BB / 64);   // 33 x 4 = 132 CTAs
    for (int t = 0; t < T_STEPS; t++) {
        aprep_kernel<<<(BB * 1024 + 255) / 256, 256>>>(X + (size_t)t * BB * DIN);
        gemm_mma<<<grid_mma, 256>>>();
        wire_kernel<<<1, 512>>>(wfw, wfb, wiw, wib);
        elem_kernel<<<(BB * HH + 255) / 256, 256>>>(out + (size_t)t * BB * HH);
    }
    tail_kernel<<<(BB * HH + 255) / 256, 256>>>(out);
}